// round 11
// baseline (speedup 1.0000x reference)
#include <cuda_runtime.h>
#include <cuda_bf16.h>
#include <math.h>
#include <stdint.h>

#define N_NODES 100000
#define IN_FEAT 128
#define HIDDEN  256
#define N_TILES 782      // ceil(100000/128)
#define GRID_P  148      // persistent CTAs

// ---------------- scratch (static device globals) ----------------
__device__ float  g_agg1[(size_t)N_NODES * IN_FEAT];    // 51.2 MB
__device__ float  g_cnt [N_NODES];
__device__ float2 g_zl  [N_NODES];
__device__ float2 g_zr  [N_NODES];
__device__ float2 g_agg2s[N_NODES];
__device__ __nv_bfloat16 g_Whi[256 * 256];              // B[n=256][k=256] (hi)
__device__ __nv_bfloat16 g_Wlo[256 * 256];              // lo

// ---------------- helpers ----------------
__device__ __forceinline__ uint32_t smem_u32(const void* p) {
    uint32_t a;
    asm("{ .reg .u64 t; cvta.to.shared.u64 t, %1; cvt.u32.u64 %0, t; }" : "=r"(a) : "l"(p));
    return a;
}
__device__ __forceinline__ void ldsm_x4(uint32_t* r, uint32_t addr) {
    asm volatile("ldmatrix.sync.aligned.m8n8.x4.shared.b16 {%0,%1,%2,%3}, [%4];"
                 : "=r"(r[0]), "=r"(r[1]), "=r"(r[2]), "=r"(r[3]) : "r"(addr));
}
__device__ __forceinline__ void mma_bf16(float* d, const uint32_t* a, uint32_t b0, uint32_t b1) {
    asm volatile("mma.sync.aligned.m16n8k16.row.col.f32.bf16.bf16.f32 "
                 "{%0,%1,%2,%3}, {%4,%5,%6,%7}, {%8,%9}, {%0,%1,%2,%3};"
                 : "+f"(d[0]), "+f"(d[1]), "+f"(d[2]), "+f"(d[3])
                 : "r"(a[0]), "r"(a[1]), "r"(a[2]), "r"(a[3]), "r"(b0), "r"(b1));
}
__device__ __forceinline__ void cp16(uint32_t sm, const void* g) {
    asm volatile("cp.async.cg.shared.global [%0], [%1], 16;" :: "r"(sm), "l"(g));
}
#define CP_COMMIT() asm volatile("cp.async.commit_group;" ::: "memory")
#define CP_WAIT0()  asm volatile("cp.async.wait_group 0;" ::: "memory")

// ---------------- SMEM map ----------------
// WHI: 128KB resident, SW128 swizzle, [4 kblk of 32KB][256 rows][128B]
#define WHI_OFF      0u
#define BL_OFF(st)   (131072u + (st) * 20480u)     // 256*80, 2 stages
#define AH_OFF(st)   (172032u + (st) * 20480u)     // 128*80 hi + 128*80 lo
#define AL_OFF(st)   (AH_OFF(st) + 10240u)
#define OFF_W2       212992u   // 4*256 f32
#define OFF_B1       217088u   // 256 f32
#define OFF_NORM     218112u   // 128 f32
#define OFF_Z        218624u   // 128*4 f32
#define OFF_INV      220672u   // 128 f32
#define SMEM_DYN     221184

// ---------------- small kernels ----------------
__global__ void k_zero() {
    const size_t n1 = (size_t)N_NODES * IN_FEAT;
    size_t stride = (size_t)gridDim.x * blockDim.x;
    size_t i0 = (size_t)blockIdx.x * blockDim.x + threadIdx.x;
    float4 z4 = make_float4(0.f, 0.f, 0.f, 0.f);
    for (size_t i = i0; i < n1 / 4; i += stride) ((float4*)g_agg1)[i] = z4;
    for (size_t i = i0; i < N_NODES; i += stride) {
        g_cnt[i] = 0.0f;
        g_agg2s[i] = make_float2(0.f, 0.f);
    }
}

__global__ void k_Wsplit(const float* __restrict__ W1l, const float* __restrict__ W1r) {
    int idx = blockIdx.x * blockDim.x + threadIdx.x;   // 0..65535
    if (idx >= 256 * 256) return;
    int h = idx >> 8, k = idx & 255;
    float v = (k < 128) ? W1l[h * 128 + k] : W1r[h * 128 + (k - 128)];
    __nv_bfloat16 hi = __float2bfloat16(v);
    __nv_bfloat16 lo = __float2bfloat16(v - __bfloat162float(hi));
    g_Whi[idx] = hi;
    g_Wlo[idx] = lo;
}

__global__ void k_scatter1(const float* __restrict__ x,
                           const int* __restrict__ src,
                           const int* __restrict__ dst, int E) {
    int gw   = (blockIdx.x * blockDim.x + threadIdx.x) >> 5;
    int lane = threadIdx.x & 31;
    if (gw >= E) return;
    int s = src[gw];
    int d = dst[gw];
    float4 v = ((const float4*)(x + (size_t)s * IN_FEAT))[lane];
    float* o = g_agg1 + (size_t)d * IN_FEAT + lane * 4;
    asm volatile("red.global.add.v4.f32 [%0], {%1, %2, %3, %4};"
                 :: "l"(o), "f"(v.x), "f"(v.y), "f"(v.z), "f"(v.w) : "memory");
    if (lane == 0)
        asm volatile("red.global.add.f32 [%0], %1;"
                     :: "l"(&g_cnt[d]), "f"(1.0f) : "memory");
}

// ---------------- persistent HMMA GEMM: M=128, N=256, W-hi resident ----------------
__global__ void __launch_bounds__(512, 1) k_gemm(const float* __restrict__ x,
                                                 const float* __restrict__ b1,
                                                 const float* __restrict__ W2l,
                                                 const float* __restrict__ W2r) {
    extern __shared__ char smem[];
    const int t    = threadIdx.x;
    const int lane = t & 31;
    const int wid  = t >> 5;
    const int wm   = wid >> 2;        // 0..3 (m strip of 32)
    const int wn   = wid & 3;         // 0..3 (n strip of 64)

    float* sW2   = (float*)(smem + OFF_W2);
    float* sB1   = (float*)(smem + OFF_B1);
    float* sNorm = (float*)(smem + OFF_NORM);
    float* sZ    = (float*)(smem + OFF_Z);
    float* sInv  = (float*)(smem + OFF_INV);

    const uint32_t smb = smem_u32(smem);

    // ---- one-time: epilogue constants + resident swizzled W-hi ----
    for (int i = t; i < 256; i += 512) sB1[i] = b1[i];
    for (int i = t; i < 1024; i += 512) {
        int m = i >> 8, k = i & 255;
        sW2[i] = (m < 2) ? W2l[m * 256 + k] : W2r[(m - 2) * 256 + k];
    }
#pragma unroll
    for (int i = 0; i < 16; i++) {
        int idx  = t + i * 512;           // 0..8191 (8192 x 16B = 128KB)
        int kblk = idx >> 11;             // 0..3
        int rr   = (idx >> 3) & 255;
        int kb   = idx & 7;               // 16B unit within 128B row
        uint32_t off = (uint32_t)(rr * 128 + kb * 16);
        uint32_t sw  = off ^ ((off >> 3) & 0x70);
        cp16(smb + WHI_OFF + (uint32_t)kblk * 32768u + sw,
             g_Whi + (size_t)rr * 256 + kblk * 64 + kb * 8);
    }
    CP_COMMIT();
    CP_WAIT0();
    __syncthreads();

    // ---- per-warp constants ----
    const uint32_t rowo = (lane & 7) + ((lane >> 3) & 1) * 8;
    const uint32_t kB   = (lane >> 4) * 16;
    const uint32_t aRel = (wm * 32 + rowo) * 80 + kB;               // A (80B padded)
    const uint32_t blRel = (wn * 64 + rowo) * 80 + kB;              // W-lo (80B padded)
    uint32_t bhiBase[4], xorv[4];
#pragma unroll
    for (int tp = 0; tp < 4; tp++) {
        uint32_t row = wn * 64 + tp * 16 + rowo;
        bhiBase[tp] = smb + WHI_OFF + row * 128;
        xorv[tp]    = (row & 7) << 4;
    }

    // ---- persistent tile loop ----
    for (int tile = blockIdx.x; tile < N_TILES; tile += GRID_P) {
        const int n0 = tile * 128;

        if (t < 128) {
            int n = n0 + t;
            sInv[t] = (n < N_NODES) ? (1.0f / fmaxf(g_cnt[n], 1.0f)) : 0.0f;
            sNorm[t] = 0.f;
            ((float4*)sZ)[t] = make_float4(0.f, 0.f, 0.f, 0.f);
        }
        __syncthreads();

        float acc[2][8][4];
#pragma unroll
        for (int a = 0; a < 2; a++)
#pragma unroll
            for (int b = 0; b < 8; b++)
#pragma unroll
                for (int c = 0; c < 4; c++) acc[a][b][c] = 0.f;

        float4 av[2];

        auto loadA = [&](int kc) {
#pragma unroll
            for (int i = 0; i < 2; i++) {
                int idx = t + i * 512;        // 0..1023
                int row = idx >> 3;           // 0..127
                int c4  = (idx & 7) * 4;
                int n   = n0 + row;
                float4 v = make_float4(0.f, 0.f, 0.f, 0.f);
                if (n < N_NODES) {
                    if (kc < 128) {
                        v = *(const float4*)(g_agg1 + (size_t)n * 128 + kc + c4);
                        float iv = sInv[row];
                        v.x *= iv; v.y *= iv; v.z *= iv; v.w *= iv;
                    } else {
                        v = *(const float4*)(x + (size_t)n * 128 + (kc - 128) + c4);
                    }
                }
                av[i] = v;
            }
        };
        auto stsA = [&](uint32_t ah_off, uint32_t al_off) {
#pragma unroll
            for (int i = 0; i < 2; i++) {
                int idx = t + i * 512;
                int row = idx >> 3;
                int c4  = (idx & 7) * 4;
                float4 v = av[i];
                __nv_bfloat16 h0 = __float2bfloat16(v.x), h1 = __float2bfloat16(v.y);
                __nv_bfloat16 h2 = __float2bfloat16(v.z), h3 = __float2bfloat16(v.w);
                __nv_bfloat16 l0 = __float2bfloat16(v.x - __bfloat162float(h0));
                __nv_bfloat16 l1 = __float2bfloat16(v.y - __bfloat162float(h1));
                __nv_bfloat16 l2 = __float2bfloat16(v.z - __bfloat162float(h2));
                __nv_bfloat16 l3 = __float2bfloat16(v.w - __bfloat162float(h3));
                uint32_t base = (uint32_t)(row * 80 + c4 * 2);
                __nv_bfloat162 p0 = __halves2bfloat162(h0, h1);
                __nv_bfloat162 p1 = __halves2bfloat162(h2, h3);
                uint2 uh; uh.x = *(uint32_t*)&p0; uh.y = *(uint32_t*)&p1;
                *(uint2*)(smem + ah_off + base) = uh;
                __nv_bfloat162 q0 = __halves2bfloat162(l0, l1);
                __nv_bfloat162 q1 = __halves2bfloat162(l2, l3);
                uint2 ul; ul.x = *(uint32_t*)&q0; ul.y = *(uint32_t*)&q1;
                *(uint2*)(smem + al_off + base) = ul;
            }
        };
        auto issueBlo = [&](int kc, uint32_t bl_off) {
#pragma unroll
            for (int i = 0; i < 2; i++) {
                int idx = t + i * 512;        // 0..1023
                int br = idx >> 2, bc = idx & 3;
                uint32_t doff = (uint32_t)(br * 80 + bc * 16);
                cp16(smb + bl_off + doff, g_Wlo + (size_t)br * 256 + kc + bc * 8);
            }
        };
        auto compute = [&](int c, uint32_t ah_off, uint32_t al_off, uint32_t bl_off) {
            const uint32_t kblkOff = (uint32_t)(c >> 1) * 32768u;
            const uint32_t cHalf   = (uint32_t)(c & 1) * 64u;
#pragma unroll
            for (int s = 0; s < 2; s++) {
                const uint32_t so = s * 32;
                uint32_t ah[2][4], al[2][4];
                ldsm_x4(ah[0], smb + ah_off + aRel + so);
                ldsm_x4(ah[1], smb + ah_off + aRel + 16 * 80 + so);
                ldsm_x4(al[0], smb + al_off + aRel + so);
                ldsm_x4(al[1], smb + al_off + aRel + 16 * 80 + so);
                const uint32_t sbyte = cHalf + so + kB;
                uint32_t bh[4][4];
#pragma unroll
                for (int tp = 0; tp < 4; tp++)
                    ldsm_x4(bh[tp], bhiBase[tp] + kblkOff + (sbyte ^ xorv[tp]));

                // hi*hi
#pragma unroll
                for (int tp = 0; tp < 4; tp++)
#pragma unroll
                    for (int tm = 0; tm < 2; tm++) {
                        mma_bf16(acc[tm][2 * tp],     ah[tm], bh[tp][0], bh[tp][2]);
                        mma_bf16(acc[tm][2 * tp + 1], ah[tm], bh[tp][1], bh[tp][3]);
                    }

                uint32_t bl[4][4];
#pragma unroll
                for (int tp = 0; tp < 4; tp++)
                    ldsm_x4(bl[tp], smb + bl_off + blRel + tp * (16 * 80) + so);

                // lo*hi
#pragma unroll
                for (int tp = 0; tp < 4; tp++)
#pragma unroll
                    for (int tm = 0; tm < 2; tm++) {
                        mma_bf16(acc[tm][2 * tp],     al[tm], bh[tp][0], bh[tp][2]);
                        mma_bf16(acc[tm][2 * tp + 1], al[tm], bh[tp][1], bh[tp][3]);
                    }
                // hi*lo
#pragma unroll
                for (int tp = 0; tp < 4; tp++)
#pragma unroll
                    for (int tm = 0; tm < 2; tm++) {
                        mma_bf16(acc[tm][2 * tp],     ah[tm], bl[tp][0], bl[tp][2]);
                        mma_bf16(acc[tm][2 * tp + 1], ah[tm], bl[tp][1], bl[tp][3]);
                    }
            }
        };

        // ---- prologue ----
        loadA(0);
        issueBlo(0, BL_OFF(0));
        CP_COMMIT();
        stsA(AH_OFF(0), AL_OFF(0));
        CP_WAIT0();
        __syncthreads();

        // ---- pipelined chunks ----
#pragma unroll
        for (int kci = 0; kci < 8; kci++) {
            const uint32_t cur = kci & 1, nxt = cur ^ 1;
            if (kci < 7) {
                loadA((kci + 1) * 32);
                issueBlo((kci + 1) * 32, BL_OFF(nxt));
                CP_COMMIT();
            }
            compute(kci, AH_OFF(cur), AL_OFF(cur), BL_OFF(cur));
            if (kci < 7) {
                stsA(AH_OFF(nxt), AL_OFF(nxt));
                CP_WAIT0();
            }
            __syncthreads();
        }

        // ---- epilogue ----
#pragma unroll
        for (int tm = 0; tm < 2; tm++) {
            float s0 = 0.f, s1 = 0.f;
#pragma unroll
            for (int tn = 0; tn < 8; tn++) {
                int c0 = wn * 64 + tn * 8 + (lane & 3) * 2;
                float b0v = sB1[c0], b1v = sB1[c0 + 1];
                acc[tm][tn][0] += b0v;
                acc[tm][tn][1] += b1v;
                acc[tm][tn][2] += b0v;
                acc[tm][tn][3] += b1v;
                s0 += acc[tm][tn][0] * acc[tm][tn][0] + acc[tm][tn][1] * acc[tm][tn][1];
                s1 += acc[tm][tn][2] * acc[tm][tn][2] + acc[tm][tn][3] * acc[tm][tn][3];
            }
            s0 += __shfl_xor_sync(0xffffffffu, s0, 1);
            s0 += __shfl_xor_sync(0xffffffffu, s0, 2);
            s1 += __shfl_xor_sync(0xffffffffu, s1, 1);
            s1 += __shfl_xor_sync(0xffffffffu, s1, 2);
            if ((lane & 3) == 0) {
                int r = wm * 32 + tm * 16 + (lane >> 2);
                atomicAdd(&sNorm[r], s0);
                atomicAdd(&sNorm[r + 8], s1);
            }
        }
        __syncthreads();
        if (t < 128) sNorm[t] = 1.0f / fmaxf(sqrtf(sNorm[t]), 1e-12f);
        __syncthreads();

#pragma unroll
        for (int tm = 0; tm < 2; tm++) {
            int rbase = wm * 32 + tm * 16 + (lane >> 2);
            float rc0 = sNorm[rbase], rc1 = sNorm[rbase + 8];
            float d0[4] = {0.f, 0.f, 0.f, 0.f};
            float d1[4] = {0.f, 0.f, 0.f, 0.f};
#pragma unroll
            for (int tn = 0; tn < 8; tn++) {
                int c0 = wn * 64 + tn * 8 + (lane & 3) * 2;
                float h00 = fmaxf(acc[tm][tn][0] * rc0, 0.f);
                float h01 = fmaxf(acc[tm][tn][1] * rc0, 0.f);
                float h10 = fmaxf(acc[tm][tn][2] * rc1, 0.f);
                float h11 = fmaxf(acc[tm][tn][3] * rc1, 0.f);
#pragma unroll
                for (int o = 0; o < 4; o++) {
                    float w0 = sW2[o * 256 + c0], w1 = sW2[o * 256 + c0 + 1];
                    d0[o] += h00 * w0 + h01 * w1;
                    d1[o] += h10 * w0 + h11 * w1;
                }
            }
#pragma unroll
            for (int o = 0; o < 4; o++) {
                d0[o] += __shfl_xor_sync(0xffffffffu, d0[o], 1);
                d0[o] += __shfl_xor_sync(0xffffffffu, d0[o], 2);
                d1[o] += __shfl_xor_sync(0xffffffffu, d1[o], 1);
                d1[o] += __shfl_xor_sync(0xffffffffu, d1[o], 2);
            }
            if ((lane & 3) == 0) {
#pragma unroll
                for (int o = 0; o < 4; o++) {
                    atomicAdd(&sZ[rbase * 4 + o], d0[o]);
                    atomicAdd(&sZ[(rbase + 8) * 4 + o], d1[o]);
                }
            }
        }
        __syncthreads();
        if (t < 128) {
            int n = n0 + t;
            if (n < N_NODES) {
                g_zl[n] = make_float2(sZ[t * 4 + 0], sZ[t * 4 + 1]);
                g_zr[n] = make_float2(sZ[t * 4 + 2], sZ[t * 4 + 3]);
            }
        }
        __syncthreads();
    }
}

// ---------------- scatter layer 2 + final ----------------
__global__ void k_scatter2(const int* __restrict__ src,
                           const int* __restrict__ dst, int E) {
    int e = blockIdx.x * blockDim.x + threadIdx.x;
    if (e >= E) return;
    int s = src[e];
    int d = dst[e];
    float2 z = g_zl[s];
    asm volatile("red.global.add.v2.f32 [%0], {%1, %2};"
                 :: "l"(&g_agg2s[d]), "f"(z.x), "f"(z.y) : "memory");
}

__global__ void k_final(const float* __restrict__ b2, float* __restrict__ out) {
    int n = blockIdx.x * blockDim.x + threadIdx.x;
    if (n >= N_NODES) return;
    float inv = 1.0f / fmaxf(g_cnt[n], 1.0f);
    float2 a = g_agg2s[n];
    float2 r = g_zr[n];
    float v0 = a.x * inv + r.x + b2[0];
    float v1 = a.y * inv + r.y + b2[1];
    float s = 1.0f / fmaxf(sqrtf(v0 * v0 + v1 * v1), 1e-12f);
    v0 *= s; v1 *= s;
    float m = fmaxf(v0, v1);
    float l = m + logf(expf(v0 - m) + expf(v1 - m));
    out[(size_t)n * 2 + 0] = v0 - l;
    out[(size_t)n * 2 + 1] = v1 - l;
}

extern "C" void kernel_launch(void* const* d_in, const int* in_sizes, int n_in,
                              void* d_out, int out_size) {
    const float* x   = (const float*)d_in[0];
    const int*   ei  = (const int*)d_in[1];
    const float* W1l = (const float*)d_in[2];
    const float* b1  = (const float*)d_in[3];
    const float* W1r = (const float*)d_in[4];
    const float* W2l = (const float*)d_in[5];
    const float* b2  = (const float*)d_in[6];
    const float* W2r = (const float*)d_in[7];
    float*       out = (float*)d_out;

    int E = in_sizes[1] / 2;
    const int* src = ei;
    const int* dst = ei + E;

    cudaFuncSetAttribute(k_gemm, cudaFuncAttributeMaxDynamicSharedMemorySize, SMEM_DYN);

    k_zero<<<592, 256>>>();
    k_Wsplit<<<256, 256>>>(W1l, W1r);
    k_scatter1<<<(E * 32 + 255) / 256, 256>>>(x, src, dst, E);
    k_gemm<<<GRID_P, 512, SMEM_DYN>>>(x, b1, W2l, W2r);
    k_scatter2<<<(E + 255) / 256, 256>>>(src, dst, E);
    k_final<<<(N_NODES + 255) / 256, 256>>>(b2, out);
}

// round 12
// speedup vs baseline: 1.2688x; 1.2688x over previous
#include <cuda_runtime.h>
#include <cuda_fp16.h>
#include <math.h>
#include <stdint.h>

#define N_NODES 100000
#define IN_FEAT 128
#define HIDDEN  256
#define N_TILES 1563   // ceil(100000/64)

// ---------------- scratch (static device globals) ----------------
__device__ float  g_agg1[(size_t)N_NODES * IN_FEAT];    // 51.2 MB
__device__ float  g_cnt [N_NODES];
__device__ float2 g_zl  [N_NODES];
__device__ float2 g_zr  [N_NODES];
__device__ float2 g_agg2s[N_NODES];
__device__ __half g_Whf[256 * 256];                     // W[n=256][k=256] fp16

// ---------------- helpers ----------------
__device__ __forceinline__ uint32_t smem_u32(const void* p) {
    uint32_t a;
    asm("{ .reg .u64 t; cvta.to.shared.u64 t, %1; cvt.u32.u64 %0, t; }" : "=r"(a) : "l"(p));
    return a;
}
__device__ __forceinline__ void ldsm_x4(uint32_t* r, uint32_t addr) {
    asm volatile("ldmatrix.sync.aligned.m8n8.x4.shared.b16 {%0,%1,%2,%3}, [%4];"
                 : "=r"(r[0]), "=r"(r[1]), "=r"(r[2]), "=r"(r[3]) : "r"(addr));
}
__device__ __forceinline__ void mma_f16(float* d, const uint32_t* a, uint32_t b0, uint32_t b1) {
    asm volatile("mma.sync.aligned.m16n8k16.row.col.f32.f16.f16.f32 "
                 "{%0,%1,%2,%3}, {%4,%5,%6,%7}, {%8,%9}, {%0,%1,%2,%3};"
                 : "+f"(d[0]), "+f"(d[1]), "+f"(d[2]), "+f"(d[3])
                 : "r"(a[0]), "r"(a[1]), "r"(a[2]), "r"(a[3]), "r"(b0), "r"(b1));
}
__device__ __forceinline__ void cp16(uint32_t sm, const void* g) {
    asm volatile("cp.async.cg.shared.global [%0], [%1], 16;" :: "r"(sm), "l"(g));
}
#define CP_COMMIT() asm volatile("cp.async.commit_group;" ::: "memory")
#define CP_WAIT0()  asm volatile("cp.async.wait_group 0;" ::: "memory")

// SMEM layout (dynamic), 80B-padded rows; double-buffered stages; M-tile=64
#define AH_OFF(st)  ((st) * 10240u)                     // 64*80 hi
#define AL_OFF(st)  ((st) * 10240u + 5120u)             // 64*80 lo
#define BH_OFF(st)  (20480u + (st) * 20480u)            // 256*80
#define OFF_W2   61440u    // 4*256 f32
#define OFF_B1   65536u    // 256 f32
#define OFF_NORM 66560u    // 64 f32
#define OFF_Z    66816u    // 64*4 f32
#define OFF_INV  67840u    // 64 f32
#define SMEM_DYN 68096

// ---------------- small kernels ----------------
__global__ void k_zero() {
    const size_t n1 = (size_t)N_NODES * IN_FEAT;
    size_t stride = (size_t)gridDim.x * blockDim.x;
    size_t i0 = (size_t)blockIdx.x * blockDim.x + threadIdx.x;
    float4 z4 = make_float4(0.f, 0.f, 0.f, 0.f);
    for (size_t i = i0; i < n1 / 4; i += stride) ((float4*)g_agg1)[i] = z4;
    for (size_t i = i0; i < N_NODES; i += stride) {
        g_cnt[i] = 0.0f;
        g_agg2s[i] = make_float2(0.f, 0.f);
    }
}

__global__ void k_Whalf(const float* __restrict__ W1l, const float* __restrict__ W1r) {
    int idx = blockIdx.x * blockDim.x + threadIdx.x;   // 0..65535
    if (idx >= 256 * 256) return;
    int h = idx >> 8, k = idx & 255;
    float v = (k < 128) ? W1l[h * 128 + k] : W1r[h * 128 + (k - 128)];
    g_Whf[idx] = __float2half(v);
}

__global__ void k_scatter1(const float* __restrict__ x,
                           const int* __restrict__ src,
                           const int* __restrict__ dst, int E) {
    int gw   = (blockIdx.x * blockDim.x + threadIdx.x) >> 5;
    int lane = threadIdx.x & 31;
    if (gw >= E) return;
    int s = src[gw];
    int d = dst[gw];
    float4 v = ((const float4*)(x + (size_t)s * IN_FEAT))[lane];
    float* o = g_agg1 + (size_t)d * IN_FEAT + lane * 4;
    asm volatile("red.global.add.v4.f32 [%0], {%1, %2, %3, %4};"
                 :: "l"(o), "f"(v.x), "f"(v.y), "f"(v.z), "f"(v.w) : "memory");
    if (lane == 0)
        asm volatile("red.global.add.f32 [%0], %1;"
                     :: "l"(&g_cnt[d]), "f"(1.0f) : "memory");
}

// ---------------- HMMA GEMM: fp16 2-term (A hi+lo, W single), M=64 x N=256 ----------------
__global__ void __launch_bounds__(256, 2) k_gemm(const float* __restrict__ x,
                                                 const float* __restrict__ b1,
                                                 const float* __restrict__ W2l,
                                                 const float* __restrict__ W2r) {
    extern __shared__ char smem[];
    const int t    = threadIdx.x;
    const int lane = t & 31;
    const int wid  = t >> 5;
    const int wm   = wid >> 2;        // 0..1 (m strip of 32)
    const int wn   = wid & 3;         // 0..3 (n strip of 64)
    const int n0   = blockIdx.x * 64;

    float* sW2   = (float*)(smem + OFF_W2);
    float* sB1   = (float*)(smem + OFF_B1);
    float* sNorm = (float*)(smem + OFF_NORM);
    float* sZ    = (float*)(smem + OFF_Z);
    float* sInv  = (float*)(smem + OFF_INV);

    sB1[t] = b1[t];
    for (int i = t; i < 1024; i += 256) {
        int m = i >> 8, k = i & 255;
        sW2[i] = (m < 2) ? W2l[m * 256 + k] : W2r[(m - 2) * 256 + k];
    }
    if (t < 64) {
        int n = n0 + t;
        sInv[t] = (n < N_NODES) ? (1.0f / fmaxf(g_cnt[n], 1.0f)) : 0.0f;
        sNorm[t] = 0.f;
        ((float4*)sZ)[t] = make_float4(0.f, 0.f, 0.f, 0.f);
    }
    __syncthreads();   // sInv visible before A conversion

    const uint32_t smb  = smem_u32(smem);
    const uint32_t rowo = (lane & 7) + ((lane >> 3) & 1) * 8;  // ldmatrix row offset
    const uint32_t kB   = (lane >> 4) * 16;                    // ldmatrix k-byte offset
    const uint32_t aBase = smb + (wm * 32 + rowo) * 80 + kB;
    const uint32_t bBase = smb + (wn * 64 + rowo) * 80 + kB;

    float acc[2][8][4];
#pragma unroll
    for (int a = 0; a < 2; a++)
#pragma unroll
        for (int b = 0; b < 8; b++)
#pragma unroll
            for (int c = 0; c < 4; c++) acc[a][b][c] = 0.f;

    // per-thread A-load geometry
    const int arow = t >> 3;             // 0..31 (+256 -> rows 32..63)
    const int ac4  = (t & 7) * 4;        // 0..28
    const int an0  = n0 + arow;
    const int an1  = n0 + arow + 32;
    const uint32_t asts = arow * 80 + ac4 * 2;

    float4 av[2];

    auto loadA = [&](int kc) {
#pragma unroll
        for (int i = 0; i < 2; i++) {
            int n = i ? an1 : an0;
            float4 v = make_float4(0.f, 0.f, 0.f, 0.f);
            if (n < N_NODES) {
                if (kc < 128) {
                    v = *(const float4*)(g_agg1 + (size_t)n * 128 + kc + ac4);
                    float iv = sInv[arow + i * 32];
                    v.x *= iv; v.y *= iv; v.z *= iv; v.w *= iv;
                } else {
                    v = *(const float4*)(x + (size_t)n * 128 + (kc - 128) + ac4);
                }
            }
            av[i] = v;
        }
    };
    auto stsA = [&](uint32_t ah_off, uint32_t al_off) {
#pragma unroll
        for (int i = 0; i < 2; i++) {
            float4 v = av[i];
            __half h0 = __float2half(v.x), h1 = __float2half(v.y);
            __half h2 = __float2half(v.z), h3 = __float2half(v.w);
            __half l0 = __float2half(v.x - __half2float(h0));
            __half l1 = __float2half(v.y - __half2float(h1));
            __half l2 = __float2half(v.z - __half2float(h2));
            __half l3 = __float2half(v.w - __half2float(h3));
            uint32_t base = asts + i * (32 * 80);
            __half2* ph = (__half2*)(smem + ah_off + base);
            ph[0] = __halves2half2(h0, h1);
            ph[1] = __halves2half2(h2, h3);
            __half2* pl = (__half2*)(smem + al_off + base);
            pl[0] = __halves2half2(l0, l1);
            pl[1] = __halves2half2(l2, l3);
        }
    };
    const int bbr = t >> 2;              // 0..63 (+64/128/192)
    const int bbc = t & 3;
    auto issueB = [&](int kc, uint32_t bh_off) {
#pragma unroll
        for (int i = 0; i < 4; i++) {
            int br = bbr + i * 64;
            uint32_t doff = (uint32_t)(br * 80 + bbc * 16);
            cp16(smb + bh_off + doff, g_Whf + (size_t)br * 256 + kc + bbc * 8);
        }
    };
    // 2-term fp16: load A hi/lo + B fragments, then 32 MMAs (16 hi + 16 lo, shared B)
    auto compute = [&](uint32_t ah_off, uint32_t al_off, uint32_t bh_off) {
#pragma unroll
        for (int s = 0; s < 2; s++) {
            const uint32_t so = s * 32;
            uint32_t ah[2][4], al[2][4];
            ldsm_x4(ah[0], aBase + so + ah_off);
            ldsm_x4(ah[1], aBase + 16 * 80 + so + ah_off);
            ldsm_x4(al[0], aBase + so + al_off);
            ldsm_x4(al[1], aBase + 16 * 80 + so + al_off);
            uint32_t bh[4][4];
#pragma unroll
            for (int tp = 0; tp < 4; tp++)
                ldsm_x4(bh[tp], bBase + tp * (16 * 80) + so + bh_off);

            // term hi
#pragma unroll
            for (int tp = 0; tp < 4; tp++)
#pragma unroll
                for (int tm = 0; tm < 2; tm++) {
                    mma_f16(acc[tm][2 * tp],     ah[tm], bh[tp][0], bh[tp][2]);
                    mma_f16(acc[tm][2 * tp + 1], ah[tm], bh[tp][1], bh[tp][3]);
                }
            // term lo (same B fragments)
#pragma unroll
            for (int tp = 0; tp < 4; tp++)
#pragma unroll
                for (int tm = 0; tm < 2; tm++) {
                    mma_f16(acc[tm][2 * tp],     al[tm], bh[tp][0], bh[tp][2]);
                    mma_f16(acc[tm][2 * tp + 1], al[tm], bh[tp][1], bh[tp][3]);
                }
        }
    };

    // ---- prologue: stage 0 ----
    loadA(0);
    issueB(0, BH_OFF(0));
    CP_COMMIT();
    stsA(AH_OFF(0), AL_OFF(0));
    CP_WAIT0();
    __syncthreads();

    // ---- fully unrolled pipelined main loop: 8 chunks of K=32 ----
#pragma unroll
    for (int kci = 0; kci < 8; kci++) {
        const uint32_t cur = kci & 1, nxt = cur ^ 1;
        if (kci < 7) {
            loadA((kci + 1) * 32);
            issueB((kci + 1) * 32, BH_OFF(nxt));
            CP_COMMIT();
        }
        compute(AH_OFF(cur), AL_OFF(cur), BH_OFF(cur));
        if (kci < 7) {
            stsA(AH_OFF(nxt), AL_OFF(nxt));
            CP_WAIT0();
        }
        __syncthreads();
    }

    // ---- epilogue ----
#pragma unroll
    for (int tm = 0; tm < 2; tm++) {
        float s0 = 0.f, s1 = 0.f;
#pragma unroll
        for (int tn = 0; tn < 8; tn++) {
            int c0 = wn * 64 + tn * 8 + (lane & 3) * 2;
            float b0v = sB1[c0], b1v = sB1[c0 + 1];
            acc[tm][tn][0] += b0v;
            acc[tm][tn][1] += b1v;
            acc[tm][tn][2] += b0v;
            acc[tm][tn][3] += b1v;
            s0 += acc[tm][tn][0] * acc[tm][tn][0] + acc[tm][tn][1] * acc[tm][tn][1];
            s1 += acc[tm][tn][2] * acc[tm][tn][2] + acc[tm][tn][3] * acc[tm][tn][3];
        }
        s0 += __shfl_xor_sync(0xffffffffu, s0, 1);
        s0 += __shfl_xor_sync(0xffffffffu, s0, 2);
        s1 += __shfl_xor_sync(0xffffffffu, s1, 1);
        s1 += __shfl_xor_sync(0xffffffffu, s1, 2);
        if ((lane & 3) == 0) {
            int r = wm * 32 + tm * 16 + (lane >> 2);
            atomicAdd(&sNorm[r], s0);
            atomicAdd(&sNorm[r + 8], s1);
        }
    }
    __syncthreads();
    if (t < 64) sNorm[t] = 1.0f / fmaxf(sqrtf(sNorm[t]), 1e-12f);
    __syncthreads();

#pragma unroll
    for (int tm = 0; tm < 2; tm++) {
        int rbase = wm * 32 + tm * 16 + (lane >> 2);
        float rc0 = sNorm[rbase], rc1 = sNorm[rbase + 8];
        float d0[4] = {0.f, 0.f, 0.f, 0.f};
        float d1[4] = {0.f, 0.f, 0.f, 0.f};
#pragma unroll
        for (int tn = 0; tn < 8; tn++) {
            int c0 = wn * 64 + tn * 8 + (lane & 3) * 2;
            float h00 = fmaxf(acc[tm][tn][0] * rc0, 0.f);
            float h01 = fmaxf(acc[tm][tn][1] * rc0, 0.f);
            float h10 = fmaxf(acc[tm][tn][2] * rc1, 0.f);
            float h11 = fmaxf(acc[tm][tn][3] * rc1, 0.f);
#pragma unroll
            for (int o = 0; o < 4; o++) {
                float w0 = sW2[o * 256 + c0], w1 = sW2[o * 256 + c0 + 1];
                d0[o] += h00 * w0 + h01 * w1;
                d1[o] += h10 * w0 + h11 * w1;
            }
        }
#pragma unroll
        for (int o = 0; o < 4; o++) {
            d0[o] += __shfl_xor_sync(0xffffffffu, d0[o], 1);
            d0[o] += __shfl_xor_sync(0xffffffffu, d0[o], 2);
            d1[o] += __shfl_xor_sync(0xffffffffu, d1[o], 1);
            d1[o] += __shfl_xor_sync(0xffffffffu, d1[o], 2);
        }
        if ((lane & 3) == 0) {
#pragma unroll
            for (int o = 0; o < 4; o++) {
                atomicAdd(&sZ[rbase * 4 + o], d0[o]);
                atomicAdd(&sZ[(rbase + 8) * 4 + o], d1[o]);
            }
        }
    }
    __syncthreads();
    if (t < 64) {
        int n = n0 + t;
        if (n < N_NODES) {
            g_zl[n] = make_float2(sZ[t * 4 + 0], sZ[t * 4 + 1]);
            g_zr[n] = make_float2(sZ[t * 4 + 2], sZ[t * 4 + 3]);
        }
    }
}

// ---------------- scatter layer 2 + final ----------------
__global__ void k_scatter2(const int* __restrict__ src,
                           const int* __restrict__ dst, int E) {
    int e = blockIdx.x * blockDim.x + threadIdx.x;
    if (e >= E) return;
    int s = src[e];
    int d = dst[e];
    float2 z = g_zl[s];
    asm volatile("red.global.add.v2.f32 [%0], {%1, %2};"
                 :: "l"(&g_agg2s[d]), "f"(z.x), "f"(z.y) : "memory");
}

__global__ void k_final(const float* __restrict__ b2, float* __restrict__ out) {
    int n = blockIdx.x * blockDim.x + threadIdx.x;
    if (n >= N_NODES) return;
    float inv = 1.0f / fmaxf(g_cnt[n], 1.0f);
    float2 a = g_agg2s[n];
    float2 r = g_zr[n];
    float v0 = a.x * inv + r.x + b2[0];
    float v1 = a.y * inv + r.y + b2[1];
    float s = 1.0f / fmaxf(sqrtf(v0 * v0 + v1 * v1), 1e-12f);
    v0 *= s; v1 *= s;
    float m = fmaxf(v0, v1);
    float l = m + logf(expf(v0 - m) + expf(v1 - m));
    out[(size_t)n * 2 + 0] = v0 - l;
    out[(size_t)n * 2 + 1] = v1 - l;
}

extern "C" void kernel_launch(void* const* d_in, const int* in_sizes, int n_in,
                              void* d_out, int out_size) {
    const float* x   = (const float*)d_in[0];
    const int*   ei  = (const int*)d_in[1];
    const float* W1l = (const float*)d_in[2];
    const float* b1  = (const float*)d_in[3];
    const float* W1r = (const float*)d_in[4];
    const float* W2l = (const float*)d_in[5];
    const float* b2  = (const float*)d_in[6];
    const float* W2r = (const float*)d_in[7];
    float*       out = (float*)d_out;

    int E = in_sizes[1] / 2;
    const int* src = ei;
    const int* dst = ei + E;

    cudaFuncSetAttribute(k_gemm, cudaFuncAttributeMaxDynamicSharedMemorySize, SMEM_DYN);

    k_zero<<<592, 256>>>();
    k_Whalf<<<256, 256>>>(W1l, W1r);
    k_scatter1<<<(E * 32 + 255) / 256, 256>>>(x, src, dst, E);
    k_gemm<<<N_TILES, 256, SMEM_DYN>>>(x, b1, W2l, W2r);
    k_scatter2<<<(E + 255) / 256, 256>>>(src, dst, E);
    k_final<<<(N_NODES + 255) / 256, 256>>>(b2, out);
}

// round 13
// speedup vs baseline: 1.4915x; 1.1756x over previous
#include <cuda_runtime.h>
#include <cuda_fp16.h>
#include <math.h>
#include <stdint.h>

#define N_NODES 100000
#define IN_FEAT 128
#define HIDDEN  256
#define N_TILES 1563   // ceil(100000/64)

// ---------------- scratch (static device globals) ----------------
__device__ float  g_agg1[(size_t)N_NODES * IN_FEAT];    // 51.2 MB
__device__ float  g_cnt [N_NODES];
__device__ float2 g_zl  [N_NODES];
__device__ float2 g_zr  [N_NODES];
__device__ float2 g_agg2s[N_NODES];
__device__ __half g_Whf[256 * 256];                     // W[n=256][k=256] fp16

// ---------------- helpers ----------------
__device__ __forceinline__ uint32_t smem_u32(const void* p) {
    uint32_t a;
    asm("{ .reg .u64 t; cvta.to.shared.u64 t, %1; cvt.u32.u64 %0, t; }" : "=r"(a) : "l"(p));
    return a;
}
__device__ __forceinline__ void ldsm_x4(uint32_t* r, uint32_t addr) {
    asm volatile("ldmatrix.sync.aligned.m8n8.x4.shared.b16 {%0,%1,%2,%3}, [%4];"
                 : "=r"(r[0]), "=r"(r[1]), "=r"(r[2]), "=r"(r[3]) : "r"(addr));
}
__device__ __forceinline__ void mma_f16(float* d, const uint32_t* a, uint32_t b0, uint32_t b1) {
    asm volatile("mma.sync.aligned.m16n8k16.row.col.f32.f16.f16.f32 "
                 "{%0,%1,%2,%3}, {%4,%5,%6,%7}, {%8,%9}, {%0,%1,%2,%3};"
                 : "+f"(d[0]), "+f"(d[1]), "+f"(d[2]), "+f"(d[3])
                 : "r"(a[0]), "r"(a[1]), "r"(a[2]), "r"(a[3]), "r"(b0), "r"(b1));
}
__device__ __forceinline__ void cp16(uint32_t sm, const void* g) {
    asm volatile("cp.async.cg.shared.global [%0], [%1], 16;" :: "r"(sm), "l"(g));
}
#define CP_COMMIT() asm volatile("cp.async.commit_group;" ::: "memory")
#define CP_WAIT0()  asm volatile("cp.async.wait_group 0;" ::: "memory")

// SMEM layout (dynamic), 80B-padded rows; double-buffered stages; M-tile=64
#define AH_OFF(st)  ((st) * 5120u)                      // 64*80, single fp16 A
#define BH_OFF(st)  (10240u + (st) * 20480u)            // 256*80
#define OFF_W2   51200u    // 4*256 f32
#define OFF_B1   55296u    // 256 f32
#define OFF_NORM 56320u    // 64 f32
#define OFF_Z    56576u    // 64*4 f32
#define OFF_INV  57600u    // 64 f32
#define SMEM_DYN 57856

// ---------------- small kernels ----------------
__global__ void k_zero() {
    const size_t n1 = (size_t)N_NODES * IN_FEAT;
    size_t stride = (size_t)gridDim.x * blockDim.x;
    size_t i0 = (size_t)blockIdx.x * blockDim.x + threadIdx.x;
    float4 z4 = make_float4(0.f, 0.f, 0.f, 0.f);
    for (size_t i = i0; i < n1 / 4; i += stride) ((float4*)g_agg1)[i] = z4;
    for (size_t i = i0; i < N_NODES; i += stride) {
        g_cnt[i] = 0.0f;
        g_agg2s[i] = make_float2(0.f, 0.f);
    }
}

__global__ void k_Whalf(const float* __restrict__ W1l, const float* __restrict__ W1r) {
    int idx = blockIdx.x * blockDim.x + threadIdx.x;   // 0..65535
    if (idx >= 256 * 256) return;
    int h = idx >> 8, k = idx & 255;
    float v = (k < 128) ? W1l[h * 128 + k] : W1r[h * 128 + (k - 128)];
    g_Whf[idx] = __float2half(v);
}

__global__ void k_scatter1(const float* __restrict__ x,
                           const int* __restrict__ src,
                           const int* __restrict__ dst, int E) {
    int gw   = (blockIdx.x * blockDim.x + threadIdx.x) >> 5;
    int lane = threadIdx.x & 31;
    if (gw >= E) return;
    int s = src[gw];
    int d = dst[gw];
    float4 v = ((const float4*)(x + (size_t)s * IN_FEAT))[lane];
    float* o = g_agg1 + (size_t)d * IN_FEAT + lane * 4;
    asm volatile("red.global.add.v4.f32 [%0], {%1, %2, %3, %4};"
                 :: "l"(o), "f"(v.x), "f"(v.y), "f"(v.z), "f"(v.w) : "memory");
    if (lane == 0)
        asm volatile("red.global.add.f32 [%0], %1;"
                     :: "l"(&g_cnt[d]), "f"(1.0f) : "memory");
}

// ---------------- HMMA GEMM: single-term fp16, M=64 x N=256, 2 CTAs/SM ----------------
__global__ void __launch_bounds__(256, 2) k_gemm(const float* __restrict__ x,
                                                 const float* __restrict__ b1,
                                                 const float* __restrict__ W2l,
                                                 const float* __restrict__ W2r) {
    extern __shared__ char smem[];
    const int t    = threadIdx.x;
    const int lane = t & 31;
    const int wid  = t >> 5;
    const int wm   = wid >> 2;        // 0..1 (m strip of 32)
    const int wn   = wid & 3;         // 0..3 (n strip of 64)
    const int n0   = blockIdx.x * 64;

    float* sW2   = (float*)(smem + OFF_W2);
    float* sB1   = (float*)(smem + OFF_B1);
    float* sNorm = (float*)(smem + OFF_NORM);
    float* sZ    = (float*)(smem + OFF_Z);
    float* sInv  = (float*)(smem + OFF_INV);

    sB1[t] = b1[t];
    for (int i = t; i < 1024; i += 256) {
        int m = i >> 8, k = i & 255;
        sW2[i] = (m < 2) ? W2l[m * 256 + k] : W2r[(m - 2) * 256 + k];
    }
    if (t < 64) {
        int n = n0 + t;
        sInv[t] = (n < N_NODES) ? (1.0f / fmaxf(g_cnt[n], 1.0f)) : 0.0f;
        sNorm[t] = 0.f;
        ((float4*)sZ)[t] = make_float4(0.f, 0.f, 0.f, 0.f);
    }
    __syncthreads();   // sInv visible before A conversion

    const uint32_t smb  = smem_u32(smem);
    const uint32_t rowo = (lane & 7) + ((lane >> 3) & 1) * 8;  // ldmatrix row offset
    const uint32_t kB   = (lane >> 4) * 16;                    // ldmatrix k-byte offset
    const uint32_t aBase = smb + (wm * 32 + rowo) * 80 + kB;
    const uint32_t bBase = smb + (wn * 64 + rowo) * 80 + kB;

    float acc[2][8][4];
#pragma unroll
    for (int a = 0; a < 2; a++)
#pragma unroll
        for (int b = 0; b < 8; b++)
#pragma unroll
            for (int c = 0; c < 4; c++) acc[a][b][c] = 0.f;

    // per-thread A-load geometry
    const int arow = t >> 3;             // 0..31 (+256 -> rows 32..63)
    const int ac4  = (t & 7) * 4;        // 0..28
    const int an0  = n0 + arow;
    const int an1  = n0 + arow + 32;
    const uint32_t asts = arow * 80 + ac4 * 2;

    float4 av[2];

    auto loadA = [&](int kc) {
#pragma unroll
        for (int i = 0; i < 2; i++) {
            int n = i ? an1 : an0;
            float4 v = make_float4(0.f, 0.f, 0.f, 0.f);
            if (n < N_NODES) {
                if (kc < 128) {
                    v = *(const float4*)(g_agg1 + (size_t)n * 128 + kc + ac4);
                    float iv = sInv[arow + i * 32];
                    v.x *= iv; v.y *= iv; v.z *= iv; v.w *= iv;
                } else {
                    v = *(const float4*)(x + (size_t)n * 128 + (kc - 128) + ac4);
                }
            }
            av[i] = v;
        }
    };
    auto stsA = [&](uint32_t ah_off) {
#pragma unroll
        for (int i = 0; i < 2; i++) {
            float4 v = av[i];
            __half h0 = __float2half(v.x), h1 = __float2half(v.y);
            __half h2 = __float2half(v.z), h3 = __float2half(v.w);
            uint32_t base = asts + i * (32 * 80);
            __half2* ph = (__half2*)(smem + ah_off + base);
            ph[0] = __halves2half2(h0, h1);
            ph[1] = __halves2half2(h2, h3);
        }
    };
    const int bbr = t >> 2;              // 0..63 (+64/128/192)
    const int bbc = t & 3;
    auto issueB = [&](int kc, uint32_t bh_off) {
#pragma unroll
        for (int i = 0; i < 4; i++) {
            int br = bbr + i * 64;
            uint32_t doff = (uint32_t)(br * 80 + bbc * 16);
            cp16(smb + bh_off + doff, g_Whf + (size_t)br * 256 + kc + bbc * 8);
        }
    };
    // single-term fp16: 16 MMAs per k16 slice, all-independent accumulators
    auto compute = [&](uint32_t ah_off, uint32_t bh_off) {
#pragma unroll
        for (int s = 0; s < 2; s++) {
            const uint32_t so = s * 32;
            uint32_t ah[2][4];
            ldsm_x4(ah[0], aBase + so + ah_off);
            ldsm_x4(ah[1], aBase + 16 * 80 + so + ah_off);
            uint32_t bh[4][4];
#pragma unroll
            for (int tp = 0; tp < 4; tp++)
                ldsm_x4(bh[tp], bBase + tp * (16 * 80) + so + bh_off);

#pragma unroll
            for (int tp = 0; tp < 4; tp++)
#pragma unroll
                for (int tm = 0; tm < 2; tm++) {
                    mma_f16(acc[tm][2 * tp],     ah[tm], bh[tp][0], bh[tp][2]);
                    mma_f16(acc[tm][2 * tp + 1], ah[tm], bh[tp][1], bh[tp][3]);
                }
        }
    };

    // ---- prologue: stage 0 ----
    loadA(0);
    issueB(0, BH_OFF(0));
    CP_COMMIT();
    stsA(AH_OFF(0));
    CP_WAIT0();
    __syncthreads();

    // ---- fully unrolled pipelined main loop: 8 chunks of K=32 ----
#pragma unroll
    for (int kci = 0; kci < 8; kci++) {
        const uint32_t cur = kci & 1, nxt = cur ^ 1;
        if (kci < 7) {
            loadA((kci + 1) * 32);
            issueB((kci + 1) * 32, BH_OFF(nxt));
            CP_COMMIT();
        }
        compute(AH_OFF(cur), BH_OFF(cur));
        if (kci < 7) {
            stsA(AH_OFF(nxt));
            CP_WAIT0();
        }
        __syncthreads();
    }

    // ---- epilogue ----
#pragma unroll
    for (int tm = 0; tm < 2; tm++) {
        float s0 = 0.f, s1 = 0.f;
#pragma unroll
        for (int tn = 0; tn < 8; tn++) {
            int c0 = wn * 64 + tn * 8 + (lane & 3) * 2;
            float b0v = sB1[c0], b1v = sB1[c0 + 1];
            acc[tm][tn][0] += b0v;
            acc[tm][tn][1] += b1v;
            acc[tm][tn][2] += b0v;
            acc[tm][tn][3] += b1v;
            s0 += acc[tm][tn][0] * acc[tm][tn][0] + acc[tm][tn][1] * acc[tm][tn][1];
            s1 += acc[tm][tn][2] * acc[tm][tn][2] + acc[tm][tn][3] * acc[tm][tn][3];
        }
        s0 += __shfl_xor_sync(0xffffffffu, s0, 1);
        s0 += __shfl_xor_sync(0xffffffffu, s0, 2);
        s1 += __shfl_xor_sync(0xffffffffu, s1, 1);
        s1 += __shfl_xor_sync(0xffffffffu, s1, 2);
        if ((lane & 3) == 0) {
            int r = wm * 32 + tm * 16 + (lane >> 2);
            atomicAdd(&sNorm[r], s0);
            atomicAdd(&sNorm[r + 8], s1);
        }
    }
    __syncthreads();
    if (t < 64) sNorm[t] = 1.0f / fmaxf(sqrtf(sNorm[t]), 1e-12f);
    __syncthreads();

#pragma unroll
    for (int tm = 0; tm < 2; tm++) {
        int rbase = wm * 32 + tm * 16 + (lane >> 2);
        float rc0 = sNorm[rbase], rc1 = sNorm[rbase + 8];
        float d0[4] = {0.f, 0.f, 0.f, 0.f};
        float d1[4] = {0.f, 0.f, 0.f, 0.f};
#pragma unroll
        for (int tn = 0; tn < 8; tn++) {
            int c0 = wn * 64 + tn * 8 + (lane & 3) * 2;
            float h00 = fmaxf(acc[tm][tn][0] * rc0, 0.f);
            float h01 = fmaxf(acc[tm][tn][1] * rc0, 0.f);
            float h10 = fmaxf(acc[tm][tn][2] * rc1, 0.f);
            float h11 = fmaxf(acc[tm][tn][3] * rc1, 0.f);
#pragma unroll
            for (int o = 0; o < 4; o++) {
                float w0 = sW2[o * 256 + c0], w1 = sW2[o * 256 + c0 + 1];
                d0[o] += h00 * w0 + h01 * w1;
                d1[o] += h10 * w0 + h11 * w1;
            }
        }
#pragma unroll
        for (int o = 0; o < 4; o++) {
            d0[o] += __shfl_xor_sync(0xffffffffu, d0[o], 1);
            d0[o] += __shfl_xor_sync(0xffffffffu, d0[o], 2);
            d1[o] += __shfl_xor_sync(0xffffffffu, d1[o], 1);
            d1[o] += __shfl_xor_sync(0xffffffffu, d1[o], 2);
        }
        if ((lane & 3) == 0) {
#pragma unroll
            for (int o = 0; o < 4; o++) {
                atomicAdd(&sZ[rbase * 4 + o], d0[o]);
                atomicAdd(&sZ[(rbase + 8) * 4 + o], d1[o]);
            }
        }
    }
    __syncthreads();
    if (t < 64) {
        int n = n0 + t;
        if (n < N_NODES) {
            g_zl[n] = make_float2(sZ[t * 4 + 0], sZ[t * 4 + 1]);
            g_zr[n] = make_float2(sZ[t * 4 + 2], sZ[t * 4 + 3]);
        }
    }
}

// ---------------- scatter layer 2 + final ----------------
__global__ void k_scatter2(const int* __restrict__ src,
                           const int* __restrict__ dst, int E) {
    int e = blockIdx.x * blockDim.x + threadIdx.x;
    if (e >= E) return;
    int s = src[e];
    int d = dst[e];
    float2 z = g_zl[s];
    asm volatile("red.global.add.v2.f32 [%0], {%1, %2};"
                 :: "l"(&g_agg2s[d]), "f"(z.x), "f"(z.y) : "memory");
}

__global__ void k_final(const float* __restrict__ b2, float* __restrict__ out) {
    int n = blockIdx.x * blockDim.x + threadIdx.x;
    if (n >= N_NODES) return;
    float inv = 1.0f / fmaxf(g_cnt[n], 1.0f);
    float2 a = g_agg2s[n];
    float2 r = g_zr[n];
    float v0 = a.x * inv + r.x + b2[0];
    float v1 = a.y * inv + r.y + b2[1];
    float s = 1.0f / fmaxf(sqrtf(v0 * v0 + v1 * v1), 1e-12f);
    v0 *= s; v1 *= s;
    float m = fmaxf(v0, v1);
    float l = m + logf(expf(v0 - m) + expf(v1 - m));
    out[(size_t)n * 2 + 0] = v0 - l;
    out[(size_t)n * 2 + 1] = v1 - l;
}

extern "C" void kernel_launch(void* const* d_in, const int* in_sizes, int n_in,
                              void* d_out, int out_size) {
    const float* x   = (const float*)d_in[0];
    const int*   ei  = (const int*)d_in[1];
    const float* W1l = (const float*)d_in[2];
    const float* b1  = (const float*)d_in[3];
    const float* W1r = (const float*)d_in[4];
    const float* W2l = (const float*)d_in[5];
    const float* b2  = (const float*)d_in[6];
    const float* W2r = (const float*)d_in[7];
    float*       out = (float*)d_out;

    int E = in_sizes[1] / 2;
    const int* src = ei;
    const int* dst = ei + E;

    cudaFuncSetAttribute(k_gemm, cudaFuncAttributeMaxDynamicSharedMemorySize, SMEM_DYN);

    k_zero<<<592, 256>>>();
    k_Whalf<<<256, 256>>>(W1l, W1r);
    k_scatter1<<<(E * 32 + 255) / 256, 256>>>(x, src, dst, E);
    k_gemm<<<N_TILES, 256, SMEM_DYN>>>(x, b1, W2l, W2r);
    k_scatter2<<<(E + 255) / 256, 256>>>(src, dst, E);
    k_final<<<(N_NODES + 255) / 256, 256>>>(b2, out);
}